// round 8
// baseline (speedup 1.0000x reference)
#include <cuda_runtime.h>
#include <math.h>
#include <stdint.h>

// Problem shapes (fixed by setup_inputs)
#define S_DIM 1024
#define B_DIM 2
#define D_DIM 1024
#define LP1   4
#define H_DIM 16
#define HD    64
#define BHD   (B_DIM * H_DIM)              // 32
#define ROWS  (B_DIM * D_DIM)              // 2048
#define M_X   (S_DIM * B_DIM)              // 2048
#define M_LO  ((LP1 - 1) * S_DIM * B_DIM)  // 6144

#define NE_X   ((size_t)M_X * D_DIM)       // 2M
#define NE_LO  ((size_t)M_LO * D_DIM)      // 6M
#define NE_W   ((size_t)D_DIM * D_DIM)     // 1M
#define NE_KV  ((size_t)LP1 * M_X * D_DIM) // 8M

// Split bf16 planes (static device scratch)
__device__ uint16_t g_xh[NE_X],  g_xl[NE_X];
__device__ uint16_t g_loh[NE_LO], g_lol[NE_LO];
__device__ uint16_t g_Wsh[4 * NE_W], g_Wsl[4 * NE_W];   // order: q,k,v,o
__device__ uint16_t g_Qh[NE_X],  g_Ql[NE_X];
__device__ uint16_t g_Kh[NE_KV], g_Kl[NE_KV];
__device__ uint16_t g_Vh[NE_KV], g_Vl[NE_KV];
__device__ uint16_t g_Ch[NE_X],  g_Cl[NE_X];

// ---------------------------------------------------------------------------
// Helpers
// ---------------------------------------------------------------------------
__device__ __forceinline__ uint32_t smem_u32(const void* p) {
    uint32_t a;
    asm("{ .reg .u64 t; cvta.to.shared.u64 t, %1; cvt.u32.u64 %0, t; }"
        : "=r"(a) : "l"(p));
    return a;
}
__device__ __forceinline__ uint32_t cvt2bf(float a, float b) {  // {lo=a, hi=b}
    uint32_t r;
    asm("cvt.rn.bf16x2.f32 %0, %1, %2;" : "=r"(r) : "f"(b), "f"(a));
    return r;
}
__device__ __forceinline__ float bflo(uint32_t p) { return __uint_as_float(p << 16); }
__device__ __forceinline__ float bfhi(uint32_t p) { return __uint_as_float(p & 0xffff0000u); }

__device__ __forceinline__ void ldmx4(uint32_t* r, uint32_t addr) {
    asm volatile("ldmatrix.sync.aligned.m8n8.x4.shared.b16 {%0,%1,%2,%3}, [%4];"
                 : "=r"(r[0]), "=r"(r[1]), "=r"(r[2]), "=r"(r[3]) : "r"(addr));
}
__device__ __forceinline__ void ldmx4t(uint32_t* r, uint32_t addr) {
    asm volatile("ldmatrix.sync.aligned.m8n8.x4.trans.shared.b16 {%0,%1,%2,%3}, [%4];"
                 : "=r"(r[0]), "=r"(r[1]), "=r"(r[2]), "=r"(r[3]) : "r"(addr));
}
__device__ __forceinline__ void ldmx2(uint32_t* r, uint32_t addr) {
    asm volatile("ldmatrix.sync.aligned.m8n8.x2.shared.b16 {%0,%1}, [%2];"
                 : "=r"(r[0]), "=r"(r[1]) : "r"(addr));
}
__device__ __forceinline__ void mma_bf16(float* d, const uint32_t* a,
                                         const uint32_t* b) {
    asm volatile(
        "mma.sync.aligned.m16n8k16.row.col.f32.bf16.bf16.f32 "
        "{%0,%1,%2,%3}, {%4,%5,%6,%7}, {%8,%9}, {%0,%1,%2,%3};"
        : "+f"(d[0]), "+f"(d[1]), "+f"(d[2]), "+f"(d[3])
        : "r"(a[0]), "r"(a[1]), "r"(a[2]), "r"(a[3]), "r"(b[0]), "r"(b[1]));
}
__device__ __forceinline__ void cp16(uint32_t dst, const void* src) {
    asm volatile("cp.async.cg.shared.global [%0], [%1], 16;"
                 :: "r"(dst), "l"(src));
}
__device__ __forceinline__ void cp_commit() {
    asm volatile("cp.async.commit_group;");
}
__device__ __forceinline__ void cp_wait1() {
    asm volatile("cp.async.wait_group 1;");
}

// ---------------------------------------------------------------------------
// Prep: split all fp32 tensors into bf16 hi/lo planes (one launch, 6 jobs).
// ---------------------------------------------------------------------------
#define NSPLIT 6
struct SplitJobs {
    const float4* src[NSPLIT];
    uint2*        dh[NSPLIT];
    uint2*        dl[NSPLIT];
    int           n4[NSPLIT];
};

__global__ void __launch_bounds__(256) split_all(SplitJobs js) {
    const int j = blockIdx.y;
    const float4* __restrict__ src = js.src[j];
    uint2* __restrict__ dh = js.dh[j];
    uint2* __restrict__ dl = js.dl[j];
    const int n4 = js.n4[j];
    for (int i = blockIdx.x * 256 + threadIdx.x; i < n4; i += gridDim.x * 256) {
        float4 v = src[i];
        uint32_t h0 = cvt2bf(v.x, v.y), h1 = cvt2bf(v.z, v.w);
        uint32_t l0 = cvt2bf(v.x - bflo(h0), v.y - bfhi(h0));
        uint32_t l1 = cvt2bf(v.z - bflo(h1), v.w - bfhi(h1));
        dh[i] = make_uint2(h0, h1);
        dl[i] = make_uint2(l0, l1);
    }
}

// ---------------------------------------------------------------------------
// Tensor-core GEMM on pre-split planes:
//   C_z[M,N] = (Ah+Al)[M,K] @ (Wh+Wl)_z[N,K]^T + bias_z
// 128x128 CTA tile, 16 warps x (32x32), K-chunk 32, 3-stage cp.async.
// ---------------------------------------------------------------------------
struct GemmJob {
    const uint16_t* Wh;
    const uint16_t* Wl;
    const float*    bias;
    float*          Cf;   // fp32 output (or null)
    uint16_t*       Ch;   // split output (or null)
    uint16_t*       Cl;
};
struct GemmJobs { GemmJob j[3]; };

#define GPADK 40
#define GPLANE (128 * GPADK)            // 5120 halves per plane per stage
#define GSTAGE (4 * GPLANE)             // 20480 halves per stage
#define GSTAGES 3
#define GEMM_SMEM2 (GSTAGES * GSTAGE * 2)  // 122880 B

__device__ __forceinline__ void g_issue(uint32_t sb, int stage,
                                        const uint16_t* Ah_, const uint16_t* Al_,
                                        const uint16_t* Wh_, const uint16_t* Wl_,
                                        int bm, int bn, int k0, int tid) {
    const uint32_t base = sb + (uint32_t)stage * (GSTAGE * 2);
    const int row = tid >> 2;            // 0..127
    const int seg = (tid & 3) * 8;       // 0,8,16,24 halves
    const uint32_t doff = (uint32_t)(row * GPADK + seg) * 2;
    const size_t aoff = (size_t)(bm + row) * D_DIM + k0 + seg;
    const size_t woff = (size_t)(bn + row) * D_DIM + k0 + seg;
    cp16(base + doff,                  Ah_ + aoff);
    cp16(base + GPLANE * 2 + doff,     Al_ + aoff);
    cp16(base + 2 * GPLANE * 2 + doff, Wh_ + woff);
    cp16(base + 3 * GPLANE * 2 + doff, Wl_ + woff);
}

__global__ void __launch_bounds__(512) gemm_mma3(const uint16_t* __restrict__ Ah_,
                                                 const uint16_t* __restrict__ Al_,
                                                 GemmJobs jobs) {
    extern __shared__ __align__(16) uint16_t sh[];
    const uint32_t sb = smem_u32(sh);

    const GemmJob job = jobs.j[blockIdx.z];
    const uint16_t* __restrict__ Wh_ = job.Wh;
    const uint16_t* __restrict__ Wl_ = job.Wl;

    const int bm   = blockIdx.y * 128;
    const int bn   = blockIdx.x * 128;
    const int tid  = threadIdx.x;
    const int wid  = tid >> 5;           // 0..15
    const int lane = tid & 31;
    const int wm   = (wid >> 2) * 32;    // warp M offset
    const int wn   = (wid & 3) * 32;     // warp N offset

    float d[2][4][4];
#pragma unroll
    for (int mi = 0; mi < 2; ++mi)
#pragma unroll
        for (int ni = 0; ni < 4; ++ni)
#pragma unroll
            for (int e = 0; e < 4; ++e) d[mi][ni][e] = 0.f;

    g_issue(sb, 0, Ah_, Al_, Wh_, Wl_, bm, bn, 0, tid);
    cp_commit();
    g_issue(sb, 1, Ah_, Al_, Wh_, Wl_, bm, bn, 32, tid);
    cp_commit();

    for (int it = 0; it < 32; ++it) {
        cp_wait1();
        __syncthreads();

        const uint32_t bufb = sb + (uint32_t)((it % 3) * GSTAGE) * 2;
#pragma unroll
        for (int ks = 0; ks < 2; ++ks) {
            const int k16 = ks * 16;
            uint32_t ah[2][4], al[2][4];
            {
                const int ar = lane & 15, ac = (lane >> 4) * 8;
#pragma unroll
                for (int mi = 0; mi < 2; ++mi) {
                    uint32_t off = (uint32_t)((wm + mi * 16 + ar) * GPADK + k16 + ac) * 2;
                    ldmx4(ah[mi], bufb + off);
                    ldmx4(al[mi], bufb + GPLANE * 2 + off);
                }
            }
            uint32_t bh[4][2], bl[4][2];
            {
                const int br = lane & 7, bc = ((lane >> 3) & 1) * 8;
#pragma unroll
                for (int ni = 0; ni < 4; ++ni) {
                    uint32_t off = (uint32_t)((wn + ni * 8 + br) * GPADK + k16 + bc) * 2;
                    ldmx2(bh[ni], bufb + 2 * GPLANE * 2 + off);
                    ldmx2(bl[ni], bufb + 3 * GPLANE * 2 + off);
                }
            }
#pragma unroll
            for (int mi = 0; mi < 2; ++mi)
#pragma unroll
                for (int ni = 0; ni < 4; ++ni) {
                    mma_bf16(d[mi][ni], ah[mi], bh[ni]);
                    mma_bf16(d[mi][ni], ah[mi], bl[ni]);
                    mma_bf16(d[mi][ni], al[mi], bh[ni]);
                }
        }

        // 3 stages: buffer (it+2)%3 == (it-1)%3, fully consumed before the
        // top-of-this-iter barrier — safe to refill without a second barrier.
        if (it + 2 < 32)
            g_issue(sb, (it + 2) % 3, Ah_, Al_, Wh_, Wl_, bm, bn, (it + 2) * 32, tid);
        cp_commit();
    }

    // ---- epilogue ----
    const int qr = lane >> 2;
    const int qc = (lane & 3) * 2;
#pragma unroll
    for (int ni = 0; ni < 4; ++ni) {
        const int n0 = bn + wn + ni * 8 + qc;
        const float bx = job.bias[n0], by = job.bias[n0 + 1];
#pragma unroll
        for (int mi = 0; mi < 2; ++mi) {
            const int m0 = bm + wm + mi * 16 + qr;
            float v0 = d[mi][ni][0] + bx, v1 = d[mi][ni][1] + by;
            float v2 = d[mi][ni][2] + bx, v3 = d[mi][ni][3] + by;
            if (job.Cf) {
                *(float2*)(job.Cf + (size_t)m0 * D_DIM + n0) = make_float2(v0, v1);
                *(float2*)(job.Cf + (size_t)(m0 + 8) * D_DIM + n0) = make_float2(v2, v3);
            }
            if (job.Ch) {
                uint32_t h0 = cvt2bf(v0, v1), h1 = cvt2bf(v2, v3);
                uint32_t l0 = cvt2bf(v0 - bflo(h0), v1 - bfhi(h0));
                uint32_t l1 = cvt2bf(v2 - bflo(h1), v3 - bfhi(h1));
                *(uint32_t*)(job.Ch + (size_t)m0 * D_DIM + n0) = h0;
                *(uint32_t*)(job.Ch + (size_t)(m0 + 8) * D_DIM + n0) = h1;
                *(uint32_t*)(job.Cl + (size_t)m0 * D_DIM + n0) = l0;
                *(uint32_t*)(job.Cl + (size_t)(m0 + 8) * D_DIM + n0) = l1;
            }
        }
    }
}

// ---------------------------------------------------------------------------
// Tensor-core flash attention on pre-split K/V planes.
// Grid (BHD, 8). 8 warps x 16 q-rows. 128-key chunks, 2-stage cp.async
// pipelined across layers. Output: split C planes (RMW across layers).
// ---------------------------------------------------------------------------
#define APD 72
#define APLANE (128 * APD)            // 9216 halves
#define ASTAGE (4 * APLANE)           // 36864 halves
#define ATTN_SMEM2 (2 * ASTAGE * 2)   // 147456 B

__device__ __forceinline__ void a_issue(uint32_t sb, int stage,
                                        const uint16_t* Kh_, const uint16_t* Kl_,
                                        const uint16_t* Vh_, const uint16_t* Vl_,
                                        int gc, int bh, int tid) {
    const uint32_t base = sb + (uint32_t)stage * (ASTAGE * 2);
    const size_t lbase = (size_t)(gc >> 3) * NE_X;          // layer offset
    const int rbase = (gc & 7) * 128;                       // key-row base
#pragma unroll
    for (int q = 0; q < 4; ++q) {
        int idx = q * 256 + tid;          // 0..1023
        int row = idx >> 3;               // 0..127
        int seg = idx & 7;                // x8 halves
        uint32_t doff = (uint32_t)(row * APD + seg * 8) * 2;
        size_t goff = lbase + (size_t)(rbase + row) * ROWS + bh * HD + seg * 8;
        cp16(base + doff,                  Kh_ + goff);
        cp16(base + APLANE * 2 + doff,     Kl_ + goff);
        cp16(base + 2 * APLANE * 2 + doff, Vh_ + goff);
        cp16(base + 3 * APLANE * 2 + doff, Vl_ + goff);
    }
}

__global__ void __launch_bounds__(256) attn_mma2(
    const uint16_t* __restrict__ Qh_, const uint16_t* __restrict__ Ql_,
    const uint16_t* __restrict__ Kh_, const uint16_t* __restrict__ Kl_,
    const uint16_t* __restrict__ Vh_, const uint16_t* __restrict__ Vl_,
    const float* __restrict__ lw_in,
    uint16_t* __restrict__ Ch_, uint16_t* __restrict__ Cl_) {
    extern __shared__ __align__(16) uint16_t ash[];
    const uint32_t sb = smem_u32(ash);

    const int bh    = blockIdx.x;
    const int qbase = blockIdx.y * 128;
    const int tid   = threadIdx.x;
    const int wid   = tid >> 5;
    const int lane  = tid & 31;
    const int wq    = wid * 16;
    const int r     = lane >> 2;
    const int c     = (lane & 3) * 2;

    // ---- Q fragments from planes (raw; scale folded into scores) ----
    uint32_t qh[4][4], ql[4][4];
#pragma unroll
    for (int s = 0; s < 4; ++s)
#pragma unroll
        for (int half = 0; half < 2; ++half)
#pragma unroll
            for (int rr = 0; rr < 2; ++rr) {
                const size_t off = (size_t)(qbase + wq + r + rr * 8) * ROWS
                                 + bh * HD + s * 16 + c + half * 8;
                qh[s][rr + half * 2] = *(const uint32_t*)(Qh_ + off);
                ql[s][rr + half * 2] = *(const uint32_t*)(Ql_ + off);
            }

    // softmax over layer weights
    float lw[LP1];
    {
        float l0 = lw_in[0], l1 = lw_in[1], l2 = lw_in[2], l3 = lw_in[3];
        float mx = fmaxf(fmaxf(l0, l1), fmaxf(l2, l3));
        float e0 = expf(l0 - mx), e1 = expf(l1 - mx);
        float e2 = expf(l2 - mx), e3 = expf(l3 - mx);
        float inv = 1.f / (e0 + e1 + e2 + e3);
        lw[0] = e0 * inv; lw[1] = e1 * inv; lw[2] = e2 * inv; lw[3] = e3 * inv;
    }

    const float sc = 0.125f * 1.44269504088896340736f;  // hd^-0.5 * log2e

    a_issue(sb, 0, Kh_, Kl_, Vh_, Vl_, 0, bh, tid);
    cp_commit();
    a_issue(sb, 1, Kh_, Kl_, Vh_, Vl_, 1, bh, tid);
    cp_commit();

    float m0 = -1e30f, m1 = -1e30f, sum0 = 0.f, sum1 = 0.f;
    float o[8][4];

    for (int gc = 0; gc < 4 * 8; ++gc) {
        if ((gc & 7) == 0) {
            m0 = m1 = -1e30f; sum0 = sum1 = 0.f;
#pragma unroll
            for (int j = 0; j < 8; ++j)
#pragma unroll
                for (int e = 0; e < 4; ++e) o[j][e] = 0.f;
        }

        cp_wait1();
        __syncthreads();
        const uint32_t bufb = sb + (uint32_t)((gc & 1) * ASTAGE) * 2;

        // ---- QK: S[16 x 128] per warp ----
        float sv[16][4];
#pragma unroll
        for (int nt2 = 0; nt2 < 8; ++nt2) {
#pragma unroll
            for (int e = 0; e < 4; ++e) {
                sv[2 * nt2][e] = 0.f;
                sv[2 * nt2 + 1][e] = 0.f;
            }
#pragma unroll
            for (int ks = 0; ks < 4; ++ks) {
                const int g = lane >> 3, r8 = lane & 7;
                const int nrow = nt2 * 16 + (g >> 1) * 8 + r8;
                const int ncol = ks * 16 + (g & 1) * 8;
                const uint32_t off = (uint32_t)(nrow * APD + ncol) * 2;
                uint32_t kbh[4], kbl[4];
                ldmx4(kbh, bufb + off);
                ldmx4(kbl, bufb + APLANE * 2 + off);
                mma_bf16(sv[2 * nt2],     qh[ks], &kbh[0]);
                mma_bf16(sv[2 * nt2],     qh[ks], &kbl[0]);
                mma_bf16(sv[2 * nt2],     ql[ks], &kbh[0]);
                mma_bf16(sv[2 * nt2 + 1], qh[ks], &kbh[2]);
                mma_bf16(sv[2 * nt2 + 1], qh[ks], &kbl[2]);
                mma_bf16(sv[2 * nt2 + 1], ql[ks], &kbh[2]);
            }
        }

        // ---- online softmax update (scores scaled by sc) ----
        float cm0 = -1e30f, cm1 = -1e30f;
#pragma unroll
        for (int nt = 0; nt < 16; ++nt) {
            cm0 = fmaxf(cm0, fmaxf(sv[nt][0], sv[nt][1]));
            cm1 = fmaxf(cm1, fmaxf(sv[nt][2], sv[nt][3]));
        }
        cm0 = fmaxf(cm0, __shfl_xor_sync(0xffffffffu, cm0, 1));
        cm0 = fmaxf(cm0, __shfl_xor_sync(0xffffffffu, cm0, 2));
        cm1 = fmaxf(cm1, __shfl_xor_sync(0xffffffffu, cm1, 1));
        cm1 = fmaxf(cm1, __shfl_xor_sync(0xffffffffu, cm1, 2));
        const float nm0 = fmaxf(m0, cm0 * sc), nm1 = fmaxf(m1, cm1 * sc);
        const float rs0 = exp2f(m0 - nm0), rs1 = exp2f(m1 - nm1);
        sum0 *= rs0; sum1 *= rs1;
#pragma unroll
        for (int j = 0; j < 8; ++j) {
            o[j][0] *= rs0; o[j][1] *= rs0;
            o[j][2] *= rs1; o[j][3] *= rs1;
        }
        m0 = nm0; m1 = nm1;

        // ---- P = exp2(S*sc - m), split, PV ----
#pragma unroll
        for (int ks2 = 0; ks2 < 8; ++ks2) {
            const int ntE = 2 * ks2, ntO = 2 * ks2 + 1;
            float p00 = exp2f(fmaf(sv[ntE][0], sc, -nm0));
            float p01 = exp2f(fmaf(sv[ntE][1], sc, -nm0));
            float p02 = exp2f(fmaf(sv[ntE][2], sc, -nm1));
            float p03 = exp2f(fmaf(sv[ntE][3], sc, -nm1));
            float p10 = exp2f(fmaf(sv[ntO][0], sc, -nm0));
            float p11 = exp2f(fmaf(sv[ntO][1], sc, -nm0));
            float p12 = exp2f(fmaf(sv[ntO][2], sc, -nm1));
            float p13 = exp2f(fmaf(sv[ntO][3], sc, -nm1));
            sum0 += (p00 + p01) + (p10 + p11);
            sum1 += (p02 + p03) + (p12 + p13);
            uint32_t ph[4], pl[4];
            ph[0] = cvt2bf(p00, p01);
            ph[1] = cvt2bf(p02, p03);
            ph[2] = cvt2bf(p10, p11);
            ph[3] = cvt2bf(p12, p13);
            pl[0] = cvt2bf(p00 - bflo(ph[0]), p01 - bfhi(ph[0]));
            pl[1] = cvt2bf(p02 - bflo(ph[1]), p03 - bfhi(ph[1]));
            pl[2] = cvt2bf(p10 - bflo(ph[2]), p11 - bfhi(ph[2]));
            pl[3] = cvt2bf(p12 - bflo(ph[3]), p13 - bfhi(ph[3]));

#pragma unroll
            for (int ntv = 0; ntv < 4; ++ntv) {
                const int g = lane >> 3, r8 = lane & 7;
                const int krow = ks2 * 16 + (g & 1) * 8 + r8;
                const int vcol = ntv * 16 + (g >> 1) * 8;
                const uint32_t off = (uint32_t)(krow * APD + vcol) * 2;
                uint32_t vbh[4], vbl[4];
                ldmx4t(vbh, bufb + 2 * APLANE * 2 + off);
                ldmx4t(vbl, bufb + 3 * APLANE * 2 + off);
                mma_bf16(o[2 * ntv],     ph, &vbh[0]);
                mma_bf16(o[2 * ntv],     ph, &vbl[0]);
                mma_bf16(o[2 * ntv],     pl, &vbh[0]);
                mma_bf16(o[2 * ntv + 1], ph, &vbh[2]);
                mma_bf16(o[2 * ntv + 1], ph, &vbl[2]);
                mma_bf16(o[2 * ntv + 1], pl, &vbh[2]);
            }
        }

        __syncthreads();
        if (gc + 2 < 32)
            a_issue(sb, gc & 1, Kh_, Kl_, Vh_, Vl_, gc + 2, bh, tid);
        cp_commit();

        // ---- end of a layer: weighted accumulate into split C planes ----
        if ((gc & 7) == 7) {
            const int l = gc >> 3;
            sum0 += __shfl_xor_sync(0xffffffffu, sum0, 1);
            sum0 += __shfl_xor_sync(0xffffffffu, sum0, 2);
            sum1 += __shfl_xor_sync(0xffffffffu, sum1, 1);
            sum1 += __shfl_xor_sync(0xffffffffu, sum1, 2);
            const float w0 = lw[l] / sum0, w1 = lw[l] / sum1;
            const int g0 = qbase + wq + r;
#pragma unroll
            for (int j = 0; j < 8; ++j) {
                size_t off0 = (size_t)g0 * ROWS + bh * HD + j * 8 + c;
                size_t off1 = (size_t)(g0 + 8) * ROWS + bh * HD + j * 8 + c;
                float v0 = w0 * o[j][0], v1 = w0 * o[j][1];
                float v2 = w1 * o[j][2], v3 = w1 * o[j][3];
                if (l != 0) {
                    uint32_t h0 = *(uint32_t*)(Ch_ + off0), l0w = *(uint32_t*)(Cl_ + off0);
                    uint32_t h1 = *(uint32_t*)(Ch_ + off1), l1w = *(uint32_t*)(Cl_ + off1);
                    v0 += bflo(h0) + bflo(l0w); v1 += bfhi(h0) + bfhi(l0w);
                    v2 += bflo(h1) + bflo(l1w); v3 += bfhi(h1) + bfhi(l1w);
                }
                uint32_t h0 = cvt2bf(v0, v1), h1 = cvt2bf(v2, v3);
                uint32_t l0w = cvt2bf(v0 - bflo(h0), v1 - bfhi(h0));
                uint32_t l1w = cvt2bf(v2 - bflo(h1), v3 - bfhi(h1));
                *(uint32_t*)(Ch_ + off0) = h0; *(uint32_t*)(Cl_ + off0) = l0w;
                *(uint32_t*)(Ch_ + off1) = h1; *(uint32_t*)(Cl_ + off1) = l1w;
            }
        }
    }
}

// ---------------------------------------------------------------------------
extern "C" void kernel_launch(void* const* d_in, const int* in_sizes, int n_in,
                              void* d_out, int out_size) {
    const float* x  = (const float*)d_in[0];
    const float* lo = (const float*)d_in[1];
    const float* Wq = (const float*)d_in[2];
    const float* bq = (const float*)d_in[3];
    const float* Wk = (const float*)d_in[4];
    const float* bk = (const float*)d_in[5];
    const float* Wv = (const float*)d_in[6];
    const float* bv = (const float*)d_in[7];
    const float* Wo = (const float*)d_in[8];
    const float* bo = (const float*)d_in[9];
    const float* lw = (const float*)d_in[10];
    float* out = (float*)d_out;

    uint16_t *xh, *xl, *loh, *lol, *Wsh, *Wsl;
    uint16_t *Qh, *Ql, *Kh, *Kl, *Vh, *Vl, *Ch, *Cl;
    cudaGetSymbolAddress((void**)&xh, g_xh);   cudaGetSymbolAddress((void**)&xl, g_xl);
    cudaGetSymbolAddress((void**)&loh, g_loh); cudaGetSymbolAddress((void**)&lol, g_lol);
    cudaGetSymbolAddress((void**)&Wsh, g_Wsh); cudaGetSymbolAddress((void**)&Wsl, g_Wsl);
    cudaGetSymbolAddress((void**)&Qh, g_Qh);   cudaGetSymbolAddress((void**)&Ql, g_Ql);
    cudaGetSymbolAddress((void**)&Kh, g_Kh);   cudaGetSymbolAddress((void**)&Kl, g_Kl);
    cudaGetSymbolAddress((void**)&Vh, g_Vh);   cudaGetSymbolAddress((void**)&Vl, g_Vl);
    cudaGetSymbolAddress((void**)&Ch, g_Ch);   cudaGetSymbolAddress((void**)&Cl, g_Cl);

    cudaFuncSetAttribute(gemm_mma3, cudaFuncAttributeMaxDynamicSharedMemorySize,
                         GEMM_SMEM2);
    cudaFuncSetAttribute(attn_mma2, cudaFuncAttributeMaxDynamicSharedMemorySize,
                         ATTN_SMEM2);

    // 0) split all inputs into bf16 hi/lo planes (single launch)
    {
        SplitJobs js;
        js.src[0] = (const float4*)x;  js.dh[0] = (uint2*)xh;  js.dl[0] = (uint2*)xl;
        js.n4[0] = (int)(NE_X / 4);
        js.src[1] = (const float4*)lo; js.dh[1] = (uint2*)loh; js.dl[1] = (uint2*)lol;
        js.n4[1] = (int)(NE_LO / 4);
        js.src[2] = (const float4*)Wq;
        js.dh[2] = (uint2*)(Wsh + 0 * NE_W); js.dl[2] = (uint2*)(Wsl + 0 * NE_W);
        js.n4[2] = (int)(NE_W / 4);
        js.src[3] = (const float4*)Wk;
        js.dh[3] = (uint2*)(Wsh + 1 * NE_W); js.dl[3] = (uint2*)(Wsl + 1 * NE_W);
        js.n4[3] = (int)(NE_W / 4);
        js.src[4] = (const float4*)Wv;
        js.dh[4] = (uint2*)(Wsh + 2 * NE_W); js.dl[4] = (uint2*)(Wsl + 2 * NE_W);
        js.n4[4] = (int)(NE_W / 4);
        js.src[5] = (const float4*)Wo;
        js.dh[5] = (uint2*)(Wsh + 3 * NE_W); js.dl[5] = (uint2*)(Wsl + 3 * NE_W);
        js.n4[5] = (int)(NE_W / 4);
        split_all<<<dim3(1024, NSPLIT), 256>>>(js);
    }

    // 1) x -> Q, K[0], V[0]  (split-plane outputs)
    {
        GemmJobs js;
        js.j[0] = { Wsh + 0 * NE_W, Wsl + 0 * NE_W, bq, nullptr, Qh, Ql };
        js.j[1] = { Wsh + 1 * NE_W, Wsl + 1 * NE_W, bk, nullptr, Kh, Kl };
        js.j[2] = { Wsh + 2 * NE_W, Wsl + 2 * NE_W, bv, nullptr, Vh, Vl };
        gemm_mma3<<<dim3(8, M_X / 128, 3), 512, GEMM_SMEM2>>>(xh, xl, js);
    }
    // 2) layer_outputs -> K[1..3], V[1..3]
    {
        GemmJobs js;
        js.j[0] = { Wsh + 1 * NE_W, Wsl + 1 * NE_W, bk, nullptr, Kh + NE_X, Kl + NE_X };
        js.j[1] = { Wsh + 2 * NE_W, Wsl + 2 * NE_W, bv, nullptr, Vh + NE_X, Vl + NE_X };
        js.j[2] = js.j[0];
        gemm_mma3<<<dim3(8, M_LO / 128, 2), 512, GEMM_SMEM2>>>(loh, lol, js);
    }
    // 3) attention -> combined split planes
    attn_mma2<<<dim3(BHD, 8), 256, ATTN_SMEM2>>>(Qh, Ql, Kh, Kl, Vh, Vl, lw, Ch, Cl);
    // 4) combined @ Wo^T + bo -> out (fp32)
    {
        GemmJobs js;
        js.j[0] = { Wsh + 3 * NE_W, Wsl + 3 * NE_W, bo, out, nullptr, nullptr };
        js.j[1] = js.j[0];
        js.j[2] = js.j[0];
        gemm_mma3<<<dim3(8, M_X / 128, 1), 512, GEMM_SMEM2>>>(Ch, Cl, js);
    }
}

// round 9
// speedup vs baseline: 1.0804x; 1.0804x over previous
#include <cuda_runtime.h>
#include <math.h>
#include <stdint.h>

// Problem shapes (fixed by setup_inputs)
#define S_DIM 1024
#define B_DIM 2
#define D_DIM 1024
#define LP1   4
#define H_DIM 16
#define HD    64
#define BHD   (B_DIM * H_DIM)              // 32
#define ROWS  (B_DIM * D_DIM)              // 2048
#define M_X   (S_DIM * B_DIM)              // 2048
#define M_LO  ((LP1 - 1) * S_DIM * B_DIM)  // 6144

#define NE_X   ((size_t)M_X * D_DIM)
#define NE_LO  ((size_t)M_LO * D_DIM)
#define NE_W   ((size_t)D_DIM * D_DIM)
#define NE_KV  ((size_t)LP1 * M_X * D_DIM)

// Split bf16 planes (static device scratch)
__device__ uint16_t g_xh[NE_X],  g_xl[NE_X];
__device__ uint16_t g_loh[NE_LO], g_lol[NE_LO];
__device__ uint16_t g_Wsh[4 * NE_W], g_Wsl[4 * NE_W];   // order: q,k,v,o
__device__ uint16_t g_Qh[NE_X],  g_Ql[NE_X];
__device__ uint16_t g_Kh[NE_KV], g_Kl[NE_KV];
__device__ uint16_t g_Vh[NE_KV], g_Vl[NE_KV];
__device__ uint16_t g_Ch[NE_X],  g_Cl[NE_X];

// ---------------------------------------------------------------------------
// Helpers
// ---------------------------------------------------------------------------
__device__ __forceinline__ uint32_t smem_u32(const void* p) {
    uint32_t a;
    asm("{ .reg .u64 t; cvta.to.shared.u64 t, %1; cvt.u32.u64 %0, t; }"
        : "=r"(a) : "l"(p));
    return a;
}
__device__ __forceinline__ uint32_t cvt2bf(float a, float b) {  // {lo=a, hi=b}
    uint32_t r;
    asm("cvt.rn.bf16x2.f32 %0, %1, %2;" : "=r"(r) : "f"(b), "f"(a));
    return r;
}
__device__ __forceinline__ float bflo(uint32_t p) { return __uint_as_float(p << 16); }
__device__ __forceinline__ float bfhi(uint32_t p) { return __uint_as_float(p & 0xffff0000u); }

__device__ __forceinline__ void ldmx4(uint32_t* r, uint32_t addr) {
    asm volatile("ldmatrix.sync.aligned.m8n8.x4.shared.b16 {%0,%1,%2,%3}, [%4];"
                 : "=r"(r[0]), "=r"(r[1]), "=r"(r[2]), "=r"(r[3]) : "r"(addr));
}
__device__ __forceinline__ void ldmx4t(uint32_t* r, uint32_t addr) {
    asm volatile("ldmatrix.sync.aligned.m8n8.x4.trans.shared.b16 {%0,%1,%2,%3}, [%4];"
                 : "=r"(r[0]), "=r"(r[1]), "=r"(r[2]), "=r"(r[3]) : "r"(addr));
}
__device__ __forceinline__ void mma_bf16(float* d, const uint32_t* a,
                                         const uint32_t* b) {
    asm volatile(
        "mma.sync.aligned.m16n8k16.row.col.f32.bf16.bf16.f32 "
        "{%0,%1,%2,%3}, {%4,%5,%6,%7}, {%8,%9}, {%0,%1,%2,%3};"
        : "+f"(d[0]), "+f"(d[1]), "+f"(d[2]), "+f"(d[3])
        : "r"(a[0]), "r"(a[1]), "r"(a[2]), "r"(a[3]), "r"(b[0]), "r"(b[1]));
}
__device__ __forceinline__ void cp16(uint32_t dst, const void* src) {
    asm volatile("cp.async.cg.shared.global [%0], [%1], 16;"
                 :: "r"(dst), "l"(src));
}
__device__ __forceinline__ void cp_commit() {
    asm volatile("cp.async.commit_group;");
}
__device__ __forceinline__ void cp_wait1() {
    asm volatile("cp.async.wait_group 1;");
}

// ---------------------------------------------------------------------------
// Prep: split all fp32 tensors into bf16 hi/lo planes (one launch, 6 jobs).
// ---------------------------------------------------------------------------
#define NSPLIT 6
struct SplitJobs {
    const float4* src[NSPLIT];
    uint2*        dh[NSPLIT];
    uint2*        dl[NSPLIT];
    int           n4[NSPLIT];
};

__global__ void __launch_bounds__(256) split_all(SplitJobs js) {
    const int j = blockIdx.y;
    const float4* __restrict__ src = js.src[j];
    uint2* __restrict__ dh = js.dh[j];
    uint2* __restrict__ dl = js.dl[j];
    const int n4 = js.n4[j];
    for (int i = blockIdx.x * 256 + threadIdx.x; i < n4; i += gridDim.x * 256) {
        float4 v = src[i];
        uint32_t h0 = cvt2bf(v.x, v.y), h1 = cvt2bf(v.z, v.w);
        uint32_t l0 = cvt2bf(v.x - bflo(h0), v.y - bfhi(h0));
        uint32_t l1 = cvt2bf(v.z - bflo(h1), v.w - bfhi(h1));
        dh[i] = make_uint2(h0, h1);
        dl[i] = make_uint2(l0, l1);
    }
}

// ---------------------------------------------------------------------------
// GEMM on pre-split planes: C_z[M,N] = (Ah+Al)@(Wh+Wl)_z^T + bias_z.
// 128x64 CTA tile, 8 warps x (32x32), K-chunk 32, 3-stage cp.async,
// 2 CTAs/SM (smem 92KB, regs ~100).
// ---------------------------------------------------------------------------
struct GemmJob {
    const uint16_t* Wh;
    const uint16_t* Wl;
    const float*    bias;
    float*          Cf;
    uint16_t*       Ch;
    uint16_t*       Cl;
};
struct GemmJobs { GemmJob j[3]; };

#define GPADK 40
#define G_AH 0
#define G_AL (128 * GPADK)
#define G_WH (256 * GPADK)
#define G_WL (320 * GPADK)
#define GSTAGE (384 * GPADK)             // 15360 halves per stage
#define GEMM_SMEM3 (3 * GSTAGE * 2)      // 92160 B

__device__ __forceinline__ void g_issue(uint32_t sb, int stage,
                                        const uint16_t* Ah_, const uint16_t* Al_,
                                        const uint16_t* Wh_, const uint16_t* Wl_,
                                        int bm, int bn, int k0, int tid) {
    const uint32_t base = sb + (uint32_t)stage * (GSTAGE * 2);
#pragma unroll
    for (int q = 0; q < 2; ++q) {
        int idx = q * 256 + tid;           // 0..511
        int row = idx >> 2;                // 0..127
        int seg = (idx & 3) * 8;
        uint32_t doff = (uint32_t)(row * GPADK + seg) * 2;
        size_t aoff = (size_t)(bm + row) * D_DIM + k0 + seg;
        cp16(base + G_AH * 2 + doff, Ah_ + aoff);
        cp16(base + G_AL * 2 + doff, Al_ + aoff);
    }
    {
        int row = tid >> 2;                // 0..63
        int seg = (tid & 3) * 8;
        uint32_t doff = (uint32_t)(row * GPADK + seg) * 2;
        size_t woff = (size_t)(bn + row) * D_DIM + k0 + seg;
        cp16(base + G_WH * 2 + doff, Wh_ + woff);
        cp16(base + G_WL * 2 + doff, Wl_ + woff);
    }
}

__global__ void __launch_bounds__(256, 2) gemm_mma4(const uint16_t* __restrict__ Ah_,
                                                    const uint16_t* __restrict__ Al_,
                                                    GemmJobs jobs) {
    extern __shared__ __align__(16) uint16_t sh[];
    const uint32_t sb = smem_u32(sh);

    const GemmJob job = jobs.j[blockIdx.z];
    const uint16_t* __restrict__ Wh_ = job.Wh;
    const uint16_t* __restrict__ Wl_ = job.Wl;

    const int bm   = blockIdx.y * 128;
    const int bn   = blockIdx.x * 64;
    const int tid  = threadIdx.x;
    const int wid  = tid >> 5;           // 0..7
    const int lane = tid & 31;
    const int wm   = (wid >> 1) * 32;    // 0,32,64,96
    const int wn   = (wid & 1) * 32;     // 0,32

    float d[2][4][4];
#pragma unroll
    for (int mi = 0; mi < 2; ++mi)
#pragma unroll
        for (int ni = 0; ni < 4; ++ni)
#pragma unroll
            for (int e = 0; e < 4; ++e) d[mi][ni][e] = 0.f;

    g_issue(sb, 0, Ah_, Al_, Wh_, Wl_, bm, bn, 0, tid);
    cp_commit();
    g_issue(sb, 1, Ah_, Al_, Wh_, Wl_, bm, bn, 32, tid);
    cp_commit();

    const int g  = lane >> 3;            // ldmatrix address group
    const int r8 = lane & 7;

    for (int it = 0; it < 32; ++it) {
        cp_wait1();
        __syncthreads();

        const uint32_t bufb = sb + (uint32_t)((it % 3) * GSTAGE) * 2;
#pragma unroll
        for (int ks = 0; ks < 2; ++ks) {
            const int k16 = ks * 16;
            uint32_t ah[2][4], al[2][4];
            {
                const int ar = lane & 15, ac = (lane >> 4) * 8;
#pragma unroll
                for (int mi = 0; mi < 2; ++mi) {
                    uint32_t off = (uint32_t)((wm + mi * 16 + ar) * GPADK + k16 + ac) * 2;
                    ldmx4(ah[mi], bufb + G_AH * 2 + off);
                    ldmx4(al[mi], bufb + G_AL * 2 + off);
                }
            }
            // B frags: one ldmx4 per 2 n8-tiles (regs [b0 t0, b1 t0, b0 t1, b1 t1])
            uint32_t bh4[2][4], bl4[2][4];
#pragma unroll
            for (int t = 0; t < 2; ++t) {
                const int row = wn + t * 16 + (g >> 1) * 8 + r8;
                const int col = k16 + (g & 1) * 8;
                uint32_t off = (uint32_t)(row * GPADK + col) * 2;
                ldmx4(bh4[t], bufb + G_WH * 2 + off);
                ldmx4(bl4[t], bufb + G_WL * 2 + off);
            }
#pragma unroll
            for (int mi = 0; mi < 2; ++mi)
#pragma unroll
                for (int ni = 0; ni < 4; ++ni) {
                    const uint32_t* bh = &bh4[ni >> 1][(ni & 1) * 2];
                    const uint32_t* bl = &bl4[ni >> 1][(ni & 1) * 2];
                    mma_bf16(d[mi][ni], ah[mi], bh);
                    mma_bf16(d[mi][ni], ah[mi], bl);
                    mma_bf16(d[mi][ni], al[mi], bh);
                }
        }

        // 3-stage: buffer (it+2)%3 was consumed in iter it-1, before this
        // iter's top barrier — safe to refill with no second barrier.
        if (it + 2 < 32)
            g_issue(sb, (it + 2) % 3, Ah_, Al_, Wh_, Wl_, bm, bn, (it + 2) * 32, tid);
        cp_commit();
    }

    // ---- epilogue ----
    const int qr = lane >> 2;
    const int qc = (lane & 3) * 2;
#pragma unroll
    for (int ni = 0; ni < 4; ++ni) {
        const int n0 = bn + wn + ni * 8 + qc;
        const float bx = job.bias[n0], by = job.bias[n0 + 1];
#pragma unroll
        for (int mi = 0; mi < 2; ++mi) {
            const int m0 = bm + wm + mi * 16 + qr;
            float v0 = d[mi][ni][0] + bx, v1 = d[mi][ni][1] + by;
            float v2 = d[mi][ni][2] + bx, v3 = d[mi][ni][3] + by;
            if (job.Cf) {
                *(float2*)(job.Cf + (size_t)m0 * D_DIM + n0) = make_float2(v0, v1);
                *(float2*)(job.Cf + (size_t)(m0 + 8) * D_DIM + n0) = make_float2(v2, v3);
            }
            if (job.Ch) {
                uint32_t h0 = cvt2bf(v0, v1), h1 = cvt2bf(v2, v3);
                uint32_t l0 = cvt2bf(v0 - bflo(h0), v1 - bfhi(h0));
                uint32_t l1 = cvt2bf(v2 - bflo(h1), v3 - bfhi(h1));
                *(uint32_t*)(job.Ch + (size_t)m0 * D_DIM + n0) = h0;
                *(uint32_t*)(job.Ch + (size_t)(m0 + 8) * D_DIM + n0) = h1;
                *(uint32_t*)(job.Cl + (size_t)m0 * D_DIM + n0) = l0;
                *(uint32_t*)(job.Cl + (size_t)(m0 + 8) * D_DIM + n0) = l1;
            }
        }
    }
}

// ---------------------------------------------------------------------------
// Flash attention on pre-split K/V planes.
// Grid (BHD, 8), 256 threads, 64-key chunks, 2-stage cp.async,
// ql tile in smem, 2 CTAs/SM (smem 92KB, regs ~118).
// ---------------------------------------------------------------------------
#define ACH 64
#define APD 72
#define APLANE (ACH * APD)              // 4608 halves per plane
#define ASTAGE (4 * APLANE)             // 18432 halves per stage
#define AQL_OFF (2 * ASTAGE)            // ql tile after the 2 stages (halves)
#define ATTN_SMEM3 ((2 * ASTAGE + 128 * APD) * 2)   // 92160 B

__device__ __forceinline__ void a_issue(uint32_t sb, int stage,
                                        const uint16_t* Kh_, const uint16_t* Kl_,
                                        const uint16_t* Vh_, const uint16_t* Vl_,
                                        int gc, int bh, int tid) {
    const uint32_t base = sb + (uint32_t)stage * (ASTAGE * 2);
    const size_t lbase = (size_t)(gc >> 4) * NE_X;
    const int rbase = (gc & 15) * ACH;
#pragma unroll
    for (int q = 0; q < 2; ++q) {
        int idx = q * 256 + tid;          // 0..511
        int row = idx >> 3;               // 0..63
        int seg = (idx & 7) * 8;
        uint32_t doff = (uint32_t)(row * APD + seg) * 2;
        size_t goff = lbase + (size_t)(rbase + row) * ROWS + bh * HD + seg;
        cp16(base + doff,                  Kh_ + goff);
        cp16(base + APLANE * 2 + doff,     Kl_ + goff);
        cp16(base + 2 * APLANE * 2 + doff, Vh_ + goff);
        cp16(base + 3 * APLANE * 2 + doff, Vl_ + goff);
    }
}

__global__ void __launch_bounds__(256, 2) attn_mma3(
    const uint16_t* __restrict__ Qh_, const uint16_t* __restrict__ Ql_,
    const uint16_t* __restrict__ Kh_, const uint16_t* __restrict__ Kl_,
    const uint16_t* __restrict__ Vh_, const uint16_t* __restrict__ Vl_,
    const float* __restrict__ lw_in,
    uint16_t* __restrict__ Ch_, uint16_t* __restrict__ Cl_) {
    extern __shared__ __align__(16) uint16_t ash[];
    const uint32_t sb = smem_u32(ash);

    const int bh    = blockIdx.x;
    const int qbase = blockIdx.y * 128;
    const int tid   = threadIdx.x;
    const int wid   = tid >> 5;
    const int lane  = tid & 31;
    const int wq    = wid * 16;
    const int r     = lane >> 2;
    const int c     = (lane & 3) * 2;
    const int g     = lane >> 3;
    const int r8    = lane & 7;

    // ---- ql tile -> smem (once), qh -> registers ----
    {
#pragma unroll
        for (int q = 0; q < 4; ++q) {
            int idx = q * 256 + tid;       // 0..1023
            int row = idx >> 3;            // 0..127
            int seg = (idx & 7) * 8;
            const uint4 v = *(const uint4*)(Ql_ + (size_t)(qbase + row) * ROWS
                                            + bh * HD + seg);
            *(uint4*)(ash + AQL_OFF + row * APD + seg) = v;
        }
    }
    uint32_t qh[4][4];
#pragma unroll
    for (int s = 0; s < 4; ++s)
#pragma unroll
        for (int half = 0; half < 2; ++half)
#pragma unroll
            for (int rr = 0; rr < 2; ++rr) {
                const size_t off = (size_t)(qbase + wq + r + rr * 8) * ROWS
                                 + bh * HD + s * 16 + c + half * 8;
                qh[s][rr + half * 2] = *(const uint32_t*)(Qh_ + off);
            }

    float lw[LP1];
    {
        float l0 = lw_in[0], l1 = lw_in[1], l2 = lw_in[2], l3 = lw_in[3];
        float mx = fmaxf(fmaxf(l0, l1), fmaxf(l2, l3));
        float e0 = expf(l0 - mx), e1 = expf(l1 - mx);
        float e2 = expf(l2 - mx), e3 = expf(l3 - mx);
        float inv = 1.f / (e0 + e1 + e2 + e3);
        lw[0] = e0 * inv; lw[1] = e1 * inv; lw[2] = e2 * inv; lw[3] = e3 * inv;
    }

    const float sc = 0.125f * 1.44269504088896340736f;

    a_issue(sb, 0, Kh_, Kl_, Vh_, Vl_, 0, bh, tid);
    cp_commit();
    a_issue(sb, 1, Kh_, Kl_, Vh_, Vl_, 1, bh, tid);
    cp_commit();

    float m0 = -1e30f, m1 = -1e30f, sum0 = 0.f, sum1 = 0.f;
    float o[8][4];

    for (int gc = 0; gc < LP1 * 16; ++gc) {
        if ((gc & 15) == 0) {
            m0 = m1 = -1e30f; sum0 = sum1 = 0.f;
#pragma unroll
            for (int j = 0; j < 8; ++j)
#pragma unroll
                for (int e = 0; e < 4; ++e) o[j][e] = 0.f;
        }

        cp_wait1();
        __syncthreads();   // also covers the one-time ql-tile writes (gc==0)
        const uint32_t bufb = sb + (uint32_t)((gc & 1) * ASTAGE) * 2;

        // ---- QK: S[16 x 64] per warp (ks outer so ql frag stays 4 regs) ----
        float sv[8][4];
#pragma unroll
        for (int j = 0; j < 8; ++j)
#pragma unroll
            for (int e = 0; e < 4; ++e) sv[j][e] = 0.f;
#pragma unroll
        for (int ks = 0; ks < 4; ++ks) {
            uint32_t qlf[4];
            {
                const int ar = lane & 15, ac = (lane >> 4) * 8;
                uint32_t off = (uint32_t)((wq + ar) * APD + ks * 16 + ac) * 2;
                ldmx4(qlf, sb + AQL_OFF * 2 + off);
            }
#pragma unroll
            for (int nt2 = 0; nt2 < 4; ++nt2) {
                const int nrow = nt2 * 16 + (g >> 1) * 8 + r8;
                const int ncol = ks * 16 + (g & 1) * 8;
                const uint32_t off = (uint32_t)(nrow * APD + ncol) * 2;
                uint32_t kbh[4], kbl[4];
                ldmx4(kbh, bufb + off);
                ldmx4(kbl, bufb + APLANE * 2 + off);
                mma_bf16(sv[2 * nt2],     qh[ks], &kbh[0]);
                mma_bf16(sv[2 * nt2],     qh[ks], &kbl[0]);
                mma_bf16(sv[2 * nt2],     qlf,    &kbh[0]);
                mma_bf16(sv[2 * nt2 + 1], qh[ks], &kbh[2]);
                mma_bf16(sv[2 * nt2 + 1], qh[ks], &kbl[2]);
                mma_bf16(sv[2 * nt2 + 1], qlf,    &kbh[2]);
            }
        }

        // ---- online softmax ----
        float cm0 = -1e30f, cm1 = -1e30f;
#pragma unroll
        for (int nt = 0; nt < 8; ++nt) {
            cm0 = fmaxf(cm0, fmaxf(sv[nt][0], sv[nt][1]));
            cm1 = fmaxf(cm1, fmaxf(sv[nt][2], sv[nt][3]));
        }
        cm0 = fmaxf(cm0, __shfl_xor_sync(0xffffffffu, cm0, 1));
        cm0 = fmaxf(cm0, __shfl_xor_sync(0xffffffffu, cm0, 2));
        cm1 = fmaxf(cm1, __shfl_xor_sync(0xffffffffu, cm1, 1));
        cm1 = fmaxf(cm1, __shfl_xor_sync(0xffffffffu, cm1, 2));
        const float nm0 = fmaxf(m0, cm0 * sc), nm1 = fmaxf(m1, cm1 * sc);
        const float rs0 = exp2f(m0 - nm0), rs1 = exp2f(m1 - nm1);
        sum0 *= rs0; sum1 *= rs1;
#pragma unroll
        for (int j = 0; j < 8; ++j) {
            o[j][0] *= rs0; o[j][1] *= rs0;
            o[j][2] *= rs1; o[j][3] *= rs1;
        }
        m0 = nm0; m1 = nm1;

        // ---- P = exp2(S*sc - m), split, PV ----
#pragma unroll
        for (int ks2 = 0; ks2 < 4; ++ks2) {
            const int ntE = 2 * ks2, ntO = 2 * ks2 + 1;
            float p00 = exp2f(fmaf(sv[ntE][0], sc, -nm0));
            float p01 = exp2f(fmaf(sv[ntE][1], sc, -nm0));
            float p02 = exp2f(fmaf(sv[ntE][2], sc, -nm1));
            float p03 = exp2f(fmaf(sv[ntE][3], sc, -nm1));
            float p10 = exp2f(fmaf(sv[ntO][0], sc, -nm0));
            float p11 = exp2f(fmaf(sv[ntO][1], sc, -nm0));
            float p12 = exp2f(fmaf(sv[ntO][2], sc, -nm1));
            float p13 = exp2f(fmaf(sv[ntO][3], sc, -nm1));
            sum0 += (p00 + p01) + (p10 + p11);
            sum1 += (p02 + p03) + (p12 + p13);
            uint32_t ph[4], pl[4];
            ph[0] = cvt2bf(p00, p01);
            ph[1] = cvt2bf(p02, p03);
            ph[2] = cvt2bf(p10, p11);
            ph[3] = cvt2bf(p12, p13);
            pl[0] = cvt2bf(p00 - bflo(ph[0]), p01 - bfhi(ph[0]));
            pl[1] = cvt2bf(p02 - bflo(ph[1]), p03 - bfhi(ph[1]));
            pl[2] = cvt2bf(p10 - bflo(ph[2]), p11 - bfhi(ph[2]));
            pl[3] = cvt2bf(p12 - bflo(ph[3]), p13 - bfhi(ph[3]));

#pragma unroll
            for (int ntv = 0; ntv < 4; ++ntv) {
                const int krow = ks2 * 16 + (g & 1) * 8 + r8;
                const int vcol = ntv * 16 + (g >> 1) * 8;
                const uint32_t off = (uint32_t)(krow * APD + vcol) * 2;
                uint32_t vbh[4], vbl[4];
                ldmx4t(vbh, bufb + 2 * APLANE * 2 + off);
                ldmx4t(vbl, bufb + 3 * APLANE * 2 + off);
                mma_bf16(o[2 * ntv],     ph, &vbh[0]);
                mma_bf16(o[2 * ntv],     ph, &vbl[0]);
                mma_bf16(o[2 * ntv],     pl, &vbh[0]);
                mma_bf16(o[2 * ntv + 1], ph, &vbh[2]);
                mma_bf16(o[2 * ntv + 1], ph, &vbl[2]);
                mma_bf16(o[2 * ntv + 1], pl, &vbh[2]);
            }
        }

        __syncthreads();
        if (gc + 2 < LP1 * 16)
            a_issue(sb, gc & 1, Kh_, Kl_, Vh_, Vl_, gc + 2, bh, tid);
        cp_commit();

        // ---- end of layer: weighted accumulate into split C planes ----
        if ((gc & 15) == 15) {
            const int l = gc >> 4;
            sum0 += __shfl_xor_sync(0xffffffffu, sum0, 1);
            sum0 += __shfl_xor_sync(0xffffffffu, sum0, 2);
            sum1 += __shfl_xor_sync(0xffffffffu, sum1, 1);
            sum1 += __shfl_xor_sync(0xffffffffu, sum1, 2);
            const float w0 = lw[l] / sum0, w1 = lw[l] / sum1;
            const int g0 = qbase + wq + r;
#pragma unroll
            for (int j = 0; j < 8; ++j) {
                size_t off0 = (size_t)g0 * ROWS + bh * HD + j * 8 + c;
                size_t off1 = (size_t)(g0 + 8) * ROWS + bh * HD + j * 8 + c;
                float v0 = w0 * o[j][0], v1 = w0 * o[j][1];
                float v2 = w1 * o[j][2], v3 = w1 * o[j][3];
                if (l != 0) {
                    uint32_t h0 = *(uint32_t*)(Ch_ + off0), l0w = *(uint32_t*)(Cl_ + off0);
                    uint32_t h1 = *(uint32_t*)(Ch_ + off1), l1w = *(uint32_t*)(Cl_ + off1);
                    v0 += bflo(h0) + bflo(l0w); v1 += bfhi(h0) + bfhi(l0w);
                    v2 += bflo(h1) + bflo(l1w); v3 += bfhi(h1) + bfhi(l1w);
                }
                uint32_t h0 = cvt2bf(v0, v1), h1 = cvt2bf(v2, v3);
                uint32_t l0w = cvt2bf(v0 - bflo(h0), v1 - bfhi(h0));
                uint32_t l1w = cvt2bf(v2 - bflo(h1), v3 - bfhi(h1));
                *(uint32_t*)(Ch_ + off0) = h0; *(uint32_t*)(Cl_ + off0) = l0w;
                *(uint32_t*)(Ch_ + off1) = h1; *(uint32_t*)(Cl_ + off1) = l1w;
            }
        }
    }
}

// ---------------------------------------------------------------------------
extern "C" void kernel_launch(void* const* d_in, const int* in_sizes, int n_in,
                              void* d_out, int out_size) {
    const float* x  = (const float*)d_in[0];
    const float* lo = (const float*)d_in[1];
    const float* Wq = (const float*)d_in[2];
    const float* bq = (const float*)d_in[3];
    const float* Wk = (const float*)d_in[4];
    const float* bk = (const float*)d_in[5];
    const float* Wv = (const float*)d_in[6];
    const float* bv = (const float*)d_in[7];
    const float* Wo = (const float*)d_in[8];
    const float* bo = (const float*)d_in[9];
    const float* lw = (const float*)d_in[10];
    float* out = (float*)d_out;

    uint16_t *xh, *xl, *loh, *lol, *Wsh, *Wsl;
    uint16_t *Qh, *Ql, *Kh, *Kl, *Vh, *Vl, *Ch, *Cl;
    cudaGetSymbolAddress((void**)&xh, g_xh);   cudaGetSymbolAddress((void**)&xl, g_xl);
    cudaGetSymbolAddress((void**)&loh, g_loh); cudaGetSymbolAddress((void**)&lol, g_lol);
    cudaGetSymbolAddress((void**)&Wsh, g_Wsh); cudaGetSymbolAddress((void**)&Wsl, g_Wsl);
    cudaGetSymbolAddress((void**)&Qh, g_Qh);   cudaGetSymbolAddress((void**)&Ql, g_Ql);
    cudaGetSymbolAddress((void**)&Kh, g_Kh);   cudaGetSymbolAddress((void**)&Kl, g_Kl);
    cudaGetSymbolAddress((void**)&Vh, g_Vh);   cudaGetSymbolAddress((void**)&Vl, g_Vl);
    cudaGetSymbolAddress((void**)&Ch, g_Ch);   cudaGetSymbolAddress((void**)&Cl, g_Cl);

    cudaFuncSetAttribute(gemm_mma4, cudaFuncAttributeMaxDynamicSharedMemorySize,
                         GEMM_SMEM3);
    cudaFuncSetAttribute(attn_mma3, cudaFuncAttributeMaxDynamicSharedMemorySize,
                         ATTN_SMEM3);

    // 0) split all inputs (single launch)
    {
        SplitJobs js;
        js.src[0] = (const float4*)x;  js.dh[0] = (uint2*)xh;  js.dl[0] = (uint2*)xl;
        js.n4[0] = (int)(NE_X / 4);
        js.src[1] = (const float4*)lo; js.dh[1] = (uint2*)loh; js.dl[1] = (uint2*)lol;
        js.n4[1] = (int)(NE_LO / 4);
        js.src[2] = (const float4*)Wq;
        js.dh[2] = (uint2*)(Wsh + 0 * NE_W); js.dl[2] = (uint2*)(Wsl + 0 * NE_W);
        js.n4[2] = (int)(NE_W / 4);
        js.src[3] = (const float4*)Wk;
        js.dh[3] = (uint2*)(Wsh + 1 * NE_W); js.dl[3] = (uint2*)(Wsl + 1 * NE_W);
        js.n4[3] = (int)(NE_W / 4);
        js.src[4] = (const float4*)Wv;
        js.dh[4] = (uint2*)(Wsh + 2 * NE_W); js.dl[4] = (uint2*)(Wsl + 2 * NE_W);
        js.n4[4] = (int)(NE_W / 4);
        js.src[5] = (const float4*)Wo;
        js.dh[5] = (uint2*)(Wsh + 3 * NE_W); js.dl[5] = (uint2*)(Wsl + 3 * NE_W);
        js.n4[5] = (int)(NE_W / 4);
        split_all<<<dim3(1024, NSPLIT), 256>>>(js);
    }

    // 1) x -> Q, K[0], V[0]
    {
        GemmJobs js;
        js.j[0] = { Wsh + 0 * NE_W, Wsl + 0 * NE_W, bq, nullptr, Qh, Ql };
        js.j[1] = { Wsh + 1 * NE_W, Wsl + 1 * NE_W, bk, nullptr, Kh, Kl };
        js.j[2] = { Wsh + 2 * NE_W, Wsl + 2 * NE_W, bv, nullptr, Vh, Vl };
        gemm_mma4<<<dim3(16, M_X / 128, 3), 256, GEMM_SMEM3>>>(xh, xl, js);
    }
    // 2) layer_outputs -> K[1..3], V[1..3]
    {
        GemmJobs js;
        js.j[0] = { Wsh + 1 * NE_W, Wsl + 1 * NE_W, bk, nullptr, Kh + NE_X, Kl + NE_X };
        js.j[1] = { Wsh + 2 * NE_W, Wsl + 2 * NE_W, bv, nullptr, Vh + NE_X, Vl + NE_X };
        js.j[2] = js.j[0];
        gemm_mma4<<<dim3(16, M_LO / 128, 2), 256, GEMM_SMEM3>>>(loh, lol, js);
    }
    // 3) attention -> combined split planes
    attn_mma3<<<dim3(BHD, 8), 256, ATTN_SMEM3>>>(Qh, Ql, Kh, Kl, Vh, Vl, lw, Ch, Cl);
    // 4) combined @ Wo^T + bo -> out
    {
        GemmJobs js;
        js.j[0] = { Wsh + 3 * NE_W, Wsl + 3 * NE_W, bo, out, nullptr, nullptr };
        js.j[1] = js.j[0];
        js.j[2] = js.j[0];
        gemm_mma4<<<dim3(16, M_X / 128, 1), 256, GEMM_SMEM3>>>(Ch, Cl, js);
    }
}